// round 1
// baseline (speedup 1.0000x reference)
#include <cuda_runtime.h>
#include <cstdint>

// Problem constants
#define BATCH   128
#define NNODES  2047
#define DIN     512
#define NLAB    64

// ---------------------------------------------------------------------------
// Scratch (device globals — no allocation allowed in kernel_launch)
// ---------------------------------------------------------------------------
__device__ float  g_emis[BATCH * NNODES * NLAB];   // 67 MB, updated in place by tree levels
__device__ float2 g_expT[NLAB * 32];               // expT pairs: [k][j] = {e^trans[j][k], e^trans[j+32][k]}

// ---------------------------------------------------------------------------
// Kernel 0: precompute exp(trans), transposed+paired for conflict-free LDS.64
// ---------------------------------------------------------------------------
__global__ void init_expT_kernel(const float* __restrict__ trans) {
    int idx = blockIdx.x * blockDim.x + threadIdx.x;
    if (idx < NLAB * 32) {
        int k = idx >> 5;
        int j = idx & 31;
        g_expT[idx] = make_float2(expf(trans[j * NLAB + k]),
                                  expf(trans[(j + 32) * NLAB + k]));
    }
}

// ---------------------------------------------------------------------------
// Kernel 1: emission GEMM  emis[r][n] = sum_k hidden[r][k]*W[k][n] + b[n]
// M = 262016, K = 512, N = 64.  tf32 mma.sync, 3-stage cp.async pipeline.
// CTA: 128 rows x 64 cols, 256 threads (8 warps, 4x2 warp grid, 32x32/warp).
// ---------------------------------------------------------------------------
#define BM 128
#define BK 16
#define ASTR 20   // 16 + 4 pad  (stride % 32 == 4 -> conflict-free frag loads)
#define WSTR 72   // 64 + 8 pad  (stride % 32 == 8 -> conflict-free frag loads)
#define STAGES 3
#define NCHUNK (DIN / BK)   // 32

__device__ __forceinline__ uint32_t f2tf32(float f) {
    uint32_t r;
    asm("cvt.rna.tf32.f32 %0, %1;" : "=r"(r) : "f"(f));
    return r;
}

__device__ __forceinline__ void mma_tf32(float* c, const uint32_t* a, const uint32_t* b) {
    asm volatile(
        "mma.sync.aligned.m16n8k8.row.col.f32.tf32.tf32.f32 "
        "{%0,%1,%2,%3}, {%4,%5,%6,%7}, {%8,%9}, {%0,%1,%2,%3};"
        : "+f"(c[0]), "+f"(c[1]), "+f"(c[2]), "+f"(c[3])
        : "r"(a[0]), "r"(a[1]), "r"(a[2]), "r"(a[3]), "r"(b[0]), "r"(b[1]));
}

__device__ __forceinline__ void cp16(uint32_t sa, const void* g) {
    asm volatile("cp.async.cg.shared.global [%0], [%1], 16;" :: "r"(sa), "l"(g));
}

__global__ __launch_bounds__(256)
void gemm_kernel(const float* __restrict__ A, const float* __restrict__ W,
                 const float* __restrict__ bias) {
    __shared__ float As[STAGES][BM * ASTR];   // 30720 B
    __shared__ float Ws[STAGES][BK * WSTR];   // 13824 B
    __shared__ float bs[NLAB];

    const int tid = threadIdx.x;
    if (tid < NLAB) bs[tid] = bias[tid];

    const int warp = tid >> 5, lane = tid & 31;
    const int wm = warp >> 1, wn = warp & 1;
    const int grp = lane >> 2, tig = lane & 3;
    const long r0 = (long)blockIdx.x * BM;

    const uint32_t as_base = (uint32_t)__cvta_generic_to_shared(&As[0][0]);
    const uint32_t ws_base = (uint32_t)__cvta_generic_to_shared(&Ws[0][0]);

    // per-thread cp.async mapping
    // A: 128 rows x 16 floats = 512 float4 -> 2 per thread
    const int a_row0 = tid >> 2;          // pass 0 row (0..63)... combined below
    // W: 16 rows x 64 floats = 256 float4 -> 1 per thread
    const int w_row = tid >> 4;           // 0..15
    const int w_c4  = tid & 15;           // 0..15

    float acc[2][4][4];
#pragma unroll
    for (int mt = 0; mt < 2; mt++)
#pragma unroll
        for (int nt = 0; nt < 4; nt++)
#pragma unroll
            for (int i = 0; i < 4; i++) acc[mt][nt][i] = 0.0f;

    // -------- load helpers (inline) --------
#define LOAD_CHUNK(chunk, stage)                                               \
    do {                                                                       \
        const float* abase = A + r0 * DIN + (chunk) * BK;                      \
        _Pragma("unroll")                                                      \
        for (int p = 0; p < 2; p++) {                                          \
            int idx = tid + p * 256;                                           \
            int row = idx >> 2;                                                \
            int c4  = idx & 3;                                                 \
            uint32_t sa = as_base + ((stage) * BM * ASTR + row * ASTR + c4 * 4) * 4; \
            cp16(sa, abase + (long)row * DIN + c4 * 4);                        \
        }                                                                      \
        {                                                                      \
            uint32_t sa = ws_base + ((stage) * BK * WSTR + w_row * WSTR + w_c4 * 4) * 4; \
            cp16(sa, W + ((chunk) * BK + w_row) * NLAB + w_c4 * 4);            \
        }                                                                      \
    } while (0)

    LOAD_CHUNK(0, 0);
    asm volatile("cp.async.commit_group;");
    LOAD_CHUNK(1, 1);
    asm volatile("cp.async.commit_group;");

    for (int kt = 0; kt < NCHUNK; kt++) {
        if (kt + 2 < NCHUNK) {
            int st = (kt + 2) % STAGES;
            LOAD_CHUNK(kt + 2, st);
        }
        asm volatile("cp.async.commit_group;");
        asm volatile("cp.async.wait_group 2;");
        __syncthreads();

        const int st = kt % STAGES;
        const float* as = As[st];
        const float* ws = Ws[st];

#pragma unroll
        for (int kk = 0; kk < 2; kk++) {
            uint32_t a[2][4], w[4][2];
#pragma unroll
            for (int mt = 0; mt < 2; mt++) {
                int rs = wm * 32 + mt * 16 + grp;
                int c = kk * 8 + tig;
                a[mt][0] = f2tf32(as[rs * ASTR + c]);
                a[mt][1] = f2tf32(as[(rs + 8) * ASTR + c]);
                a[mt][2] = f2tf32(as[rs * ASTR + c + 4]);
                a[mt][3] = f2tf32(as[(rs + 8) * ASTR + c + 4]);
            }
#pragma unroll
            for (int nt = 0; nt < 4; nt++) {
                int n = wn * 32 + nt * 8 + grp;
                int k0 = kk * 8 + tig;
                w[nt][0] = f2tf32(ws[k0 * WSTR + n]);
                w[nt][1] = f2tf32(ws[(k0 + 4) * WSTR + n]);
            }
#pragma unroll
            for (int mt = 0; mt < 2; mt++)
#pragma unroll
                for (int nt = 0; nt < 4; nt++)
                    mma_tf32(acc[mt][nt], a[mt], w[nt]);
        }
        __syncthreads();
    }

    // epilogue: + bias, write emis
#pragma unroll
    for (int mt = 0; mt < 2; mt++) {
#pragma unroll
        for (int nt = 0; nt < 4; nt++) {
            int col = wn * 32 + nt * 8 + tig * 2;
            float b0 = bs[col], b1 = bs[col + 1];
            long row = r0 + wm * 32 + mt * 16 + grp;
            float2 v0 = make_float2(acc[mt][nt][0] + b0, acc[mt][nt][1] + b1);
            float2 v1 = make_float2(acc[mt][nt][2] + b0, acc[mt][nt][3] + b1);
            *(float2*)(g_emis + row * NLAB + col) = v0;
            *(float2*)(g_emis + (row + 8) * NLAB + col) = v1;
        }
    }
#undef LOAD_CHUNK
}

// ---------------------------------------------------------------------------
// Kernel 2: one tree level.  One warp per (batch, node).
// inside[g] = emis[g] + (mL + log(expT @ exp(L-mL))) + (mR + log(expT @ exp(R-mR)))
// Updates g_emis in place; root level writes d_out instead.
// ---------------------------------------------------------------------------
__global__ __launch_bounds__(256)
void tree_kernel(int n, int shift, float* __restrict__ outp) {
    __shared__ float2 Ep[NLAB * 32];   // 16 KB: expT pairs
    __shared__ float2 es[8 * NLAB];    // 4 KB: per-warp exp vectors {eL, eR}

    const int tid = threadIdx.x;
    for (int i = tid; i < NLAB * 32; i += 256) Ep[i] = g_expT[i];
    __syncthreads();

    const int w = tid >> 5, lane = tid & 31;
    const int gw = blockIdx.x * 8 + w;
    const int b = gw >> shift;
    const int i = gw & (n - 1);
    const int gnode = n - 1 + i;

    float* base = g_emis + (long)b * (NNODES * NLAB);
    const float* rl = base + (2 * gnode + 1) * NLAB;
    const float* rr = base + (2 * gnode + 2) * NLAB;

    float L0 = rl[lane], L1 = rl[lane + 32];
    float R0 = rr[lane], R1 = rr[lane + 32];

    float mL = fmaxf(L0, L1), mR = fmaxf(R0, R1);
#pragma unroll
    for (int o = 16; o > 0; o >>= 1) {
        mL = fmaxf(mL, __shfl_xor_sync(0xffffffffu, mL, o));
        mR = fmaxf(mR, __shfl_xor_sync(0xffffffffu, mR, o));
    }

    float eL0 = __expf(L0 - mL), eL1 = __expf(L1 - mL);
    float eR0 = __expf(R0 - mR), eR1 = __expf(R1 - mR);
    es[w * NLAB + lane]      = make_float2(eL0, eR0);
    es[w * NLAB + lane + 32] = make_float2(eL1, eR1);
    __syncwarp();

    float aL0 = 0.f, aL1 = 0.f, aR0 = 0.f, aR1 = 0.f;
#pragma unroll
    for (int k = 0; k < NLAB; k++) {
        float2 t = Ep[k * 32 + lane];   // {T[lane][k], T[lane+32][k]}
        float2 e = es[w * NLAB + k];    // {eL[k], eR[k]}
        aL0 = fmaf(t.x, e.x, aL0);
        aL1 = fmaf(t.y, e.x, aL1);
        aR0 = fmaf(t.x, e.y, aR0);
        aR1 = fmaf(t.y, e.y, aR1);
    }

    float o0 = mL + __logf(aL0) + mR + __logf(aR0);
    float o1 = mL + __logf(aL1) + mR + __logf(aR1);

    const float* er = base + gnode * NLAB;
    if (outp) {
        outp[b * NLAB + lane]      = er[lane] + o0;
        outp[b * NLAB + lane + 32] = er[lane + 32] + o1;
    } else {
        float* wr = base + gnode * NLAB;
        wr[lane]      = er[lane] + o0;
        wr[lane + 32] = er[lane + 32] + o1;
    }
}

// ---------------------------------------------------------------------------
// Launcher
// ---------------------------------------------------------------------------
extern "C" void kernel_launch(void* const* d_in, const int* in_sizes, int n_in,
                              void* d_out, int out_size) {
    const float* hidden = (const float*)d_in[0];
    const float* W      = (const float*)d_in[1];
    const float* bias   = (const float*)d_in[2];
    const float* trans  = (const float*)d_in[3];
    float* out = (float*)d_out;

    init_expT_kernel<<<8, 256>>>(trans);
    gemm_kernel<<<NNODES, 256>>>(hidden, W, bias);

    for (int n = 512; n >= 1; n >>= 1) {
        int shift = 0;
        for (int t = n; t > 1; t >>= 1) shift++;
        int blocks = (BATCH * n) / 8;   // one warp per (batch, node), 8 warps/block
        tree_kernel<<<blocks, 256>>>(n, shift, (n == 1) ? out : nullptr);
    }
}

// round 3
// speedup vs baseline: 1.3942x; 1.3942x over previous
#include <cuda_runtime.h>
#include <cuda_bf16.h>
#include <cstdint>

// Problem constants
#define BATCH   128
#define NNODES  2047
#define DIN     512
#define NLAB    64

// ---------------------------------------------------------------------------
// Scratch (device globals — no allocation allowed)
// ---------------------------------------------------------------------------
__device__ float         g_emis[BATCH * NNODES * NLAB];  // 67 MB, updated in place
__device__ float2        g_expT[NLAB * 32];              // [k][lane] = {e^T[lane][k], e^T[lane+32][k]}
__device__ __nv_bfloat16 g_Wbf[DIN * NLAB];              // W as bf16, [k][n] row-major

// ---------------------------------------------------------------------------
// Kernel 0a: expT pairs for the tree kernel
// ---------------------------------------------------------------------------
__global__ void init_expT_kernel(const float* __restrict__ trans) {
    int idx = blockIdx.x * blockDim.x + threadIdx.x;
    if (idx < NLAB * 32) {
        int k = idx >> 5, j = idx & 31;
        g_expT[idx] = make_float2(expf(trans[j * NLAB + k]),
                                  expf(trans[(j + 32) * NLAB + k]));
    }
}

// Kernel 0b: W f32 -> bf16 (same [k][n] layout)
__global__ void init_Wbf_kernel(const float* __restrict__ W) {
    int idx = blockIdx.x * blockDim.x + threadIdx.x;
    if (idx < DIN * NLAB) g_Wbf[idx] = __float2bfloat16(W[idx]);
}

// ---------------------------------------------------------------------------
// GEMM: emis = hidden @ W + b.   M=262016, K=512, N=64.
// bf16 mma.sync m16n8k16 + ldmatrix.x4.  CTA: 128 rows x 64 cols, 8 warps
// (4x2 grid, 32x32 per warp).  BK=32, 16 chunks, double-buffered smem,
// register prefetch of the next chunk.
// ---------------------------------------------------------------------------
#define BM   128
#define BK   32
#define ASTR 40   // bf16 units; 80B row stride -> conflict-free LDSM (5r mod 8 perm)
#define BSTR 72   // bf16 units; 144B row stride -> conflict-free LDSM (9r mod 8 perm)
#define NCH  (DIN / BK)   // 16

__device__ __forceinline__ uint32_t smem_u32(const void* p) {
    uint32_t a;
    asm("{ .reg .u64 t; cvta.to.shared.u64 t, %1; cvt.u32.u64 %0, t; }" : "=r"(a) : "l"(p));
    return a;
}
__device__ __forceinline__ void ldsm_x4(uint32_t* r, uint32_t addr) {
    asm volatile("ldmatrix.sync.aligned.m8n8.x4.shared.b16 {%0,%1,%2,%3}, [%4];"
                 : "=r"(r[0]), "=r"(r[1]), "=r"(r[2]), "=r"(r[3]) : "r"(addr));
}
__device__ __forceinline__ void ldsm_x4_t(uint32_t* r, uint32_t addr) {
    asm volatile("ldmatrix.sync.aligned.m8n8.x4.trans.shared.b16 {%0,%1,%2,%3}, [%4];"
                 : "=r"(r[0]), "=r"(r[1]), "=r"(r[2]), "=r"(r[3]) : "r"(addr));
}
__device__ __forceinline__ void mma_bf16(float* c, const uint32_t* a, const uint32_t* b) {
    asm volatile(
        "mma.sync.aligned.m16n8k16.row.col.f32.bf16.bf16.f32 "
        "{%0,%1,%2,%3}, {%4,%5,%6,%7}, {%8,%9}, {%0,%1,%2,%3};"
        : "+f"(c[0]), "+f"(c[1]), "+f"(c[2]), "+f"(c[3])
        : "r"(a[0]), "r"(a[1]), "r"(a[2]), "r"(a[3]), "r"(b[0]), "r"(b[1]));
}

__global__ __launch_bounds__(256)
void gemm_kernel(const float* __restrict__ A, const float* __restrict__ bias) {
    __shared__ __nv_bfloat16 As[2][BM * ASTR];   // 2 x 10240 B
    __shared__ __nv_bfloat16 Ws[2][BK * BSTR];   // 2 x  4608 B
    __shared__ float bs[NLAB];

    const int tid = threadIdx.x;
    if (tid < NLAB) bs[tid] = bias[tid];

    const int warp = tid >> 5, lane = tid & 31;
    const int wm = warp >> 1, wn = warp & 1;
    const int grp = lane >> 2, tig = lane & 3;
    const long r0 = (long)blockIdx.x * BM;

    // global-load mapping
    const int a_row = tid >> 3;          // +64 per pass, 8 threads/row
    const int a_c4  = tid & 7;           // float4 index within 32-float chunk row
    const int w_row = tid >> 3;          // 0..31
    const int w_j   = (tid & 7) * 2;     // uint2 index (4 bf16 each), 16/row

    const float4* Ag = (const float4*)(A + r0 * DIN);
    const uint2*  Wg = (const uint2*)g_Wbf;     // 16 uint2 per k-row

    float acc[2][4][4];
#pragma unroll
    for (int mt = 0; mt < 2; mt++)
#pragma unroll
        for (int nb = 0; nb < 4; nb++)
#pragma unroll
            for (int i = 0; i < 4; i++) acc[mt][nb][i] = 0.0f;

    float4 va[4];
    uint2  vw[2];

#define LOAD_REGS(c)                                                    \
    do {                                                                \
        _Pragma("unroll")                                               \
        for (int p = 0; p < 4; p++)                                     \
            va[p] = Ag[(long)(a_row + p * 32) * (DIN / 4) + (c) * 8 + a_c4]; \
        vw[0] = Wg[((c) * BK + w_row) * 16 + w_j];                      \
        vw[1] = Wg[((c) * BK + w_row) * 16 + w_j + 1];                  \
    } while (0)

#define STORE_SMEM(buf)                                                 \
    do {                                                                \
        _Pragma("unroll")                                               \
        for (int p = 0; p < 4; p++) {                                   \
            __nv_bfloat162 b01 = __floats2bfloat162_rn(va[p].x, va[p].y); \
            __nv_bfloat162 b23 = __floats2bfloat162_rn(va[p].z, va[p].w); \
            uint2 pk; memcpy(&pk.x, &b01, 4); memcpy(&pk.y, &b23, 4);   \
            *(uint2*)&As[buf][(a_row + p * 32) * ASTR + a_c4 * 4] = pk; \
        }                                                               \
        *(uint2*)&Ws[buf][w_row * BSTR + w_j * 4]     = vw[0];          \
        *(uint2*)&Ws[buf][w_row * BSTR + w_j * 4 + 4] = vw[1];          \
    } while (0)

    LOAD_REGS(0);
    STORE_SMEM(0);
    __syncthreads();

#pragma unroll 2
    for (int c = 0; c < NCH; c++) {
        const int s = c & 1;
        if (c + 1 < NCH) LOAD_REGS(c + 1);

        // compute chunk c from smem buffer s
        const uint32_t as_b = smem_u32(&As[s][0]);
        const uint32_t ws_b = smem_u32(&Ws[s][0]);
#pragma unroll
        for (int kk = 0; kk < 2; kk++) {
            uint32_t a[2][4], bbv[2][4];
#pragma unroll
            for (int mt = 0; mt < 2; mt++) {
                int r = wm * 32 + mt * 16 + (lane & 15);
                int kc = kk * 16 + ((lane >> 4) << 3);
                ldsm_x4(a[mt], as_b + (uint32_t)(r * ASTR + kc) * 2);
            }
#pragma unroll
            for (int nt = 0; nt < 2; nt++) {
                int kr = kk * 16 + (lane & 15);
                int nc = wn * 32 + nt * 16 + ((lane >> 4) << 3);
                ldsm_x4_t(bbv[nt], ws_b + (uint32_t)(kr * BSTR + nc) * 2);
            }
#pragma unroll
            for (int mt = 0; mt < 2; mt++)
#pragma unroll
                for (int nt = 0; nt < 2; nt++) {
                    mma_bf16(acc[mt][nt * 2],     a[mt], &bbv[nt][0]);
                    mma_bf16(acc[mt][nt * 2 + 1], a[mt], &bbv[nt][2]);
                }
        }

        if (c + 1 < NCH) {
            STORE_SMEM((c + 1) & 1);
            __syncthreads();
        }
    }
#undef LOAD_REGS
#undef STORE_SMEM

    // epilogue: + bias, write emis (f32)
#pragma unroll
    for (int mt = 0; mt < 2; mt++) {
#pragma unroll
        for (int nb = 0; nb < 4; nb++) {
            int col = wn * 32 + nb * 8 + tig * 2;
            float b0 = bs[col], b1 = bs[col + 1];
            long row = r0 + wm * 32 + mt * 16 + grp;
            float2 v0 = make_float2(acc[mt][nb][0] + b0, acc[mt][nb][1] + b1);
            float2 v1 = make_float2(acc[mt][nb][2] + b0, acc[mt][nb][3] + b1);
            *(float2*)(g_emis + row * NLAB + col) = v0;
            *(float2*)(g_emis + (row + 8) * NLAB + col) = v1;
        }
    }
}

// ---------------------------------------------------------------------------
// Tree level kernel. One warp per PAIR of nodes (4 children).
// inside[g] = emis[g] + (mL + log(expT @ exp(L-mL))) + (mR + log(expT @ exp(R-mR)))
// ---------------------------------------------------------------------------
__global__ __launch_bounds__(256)
void tree_kernel(int n, int P, int logP, float* __restrict__ outp) {
    __shared__ float2 Ep[NLAB * 32];   // 16 KB
    __shared__ float4 es4[8 * NLAB];   // 8 KB: per-warp e vectors, [k] = {e0,e1,e2,e3}

    const int tid = threadIdx.x;
    for (int i = tid; i < NLAB * 32; i += 256) Ep[i] = g_expT[i];
    __syncthreads();

    const int w = tid >> 5, lane = tid & 31;
    const int gw = blockIdx.x * 8 + w;
    const int b = gw >> logP;
    const int j = gw & (P - 1);
    const int g0 = n - 1 + 2 * j;

    float* base = g_emis + (size_t)b * (NNODES * NLAB);
    const float* child = base + (size_t)(2 * g0 + 1) * NLAB;

    float v0[4], v1[4], m[4];
#pragma unroll
    for (int c = 0; c < 4; c++) {
        int cc = (n > 1) ? c : (c & 1);
        v0[c] = child[cc * NLAB + lane];
        v1[c] = child[cc * NLAB + lane + 32];
        m[c] = fmaxf(v0[c], v1[c]);
    }
#pragma unroll
    for (int o = 16; o > 0; o >>= 1) {
#pragma unroll
        for (int c = 0; c < 4; c++)
            m[c] = fmaxf(m[c], __shfl_xor_sync(0xffffffffu, m[c], o));
    }
    float4 e0, e1;
    e0.x = __expf(v0[0] - m[0]); e0.y = __expf(v0[1] - m[1]);
    e0.z = __expf(v0[2] - m[2]); e0.w = __expf(v0[3] - m[3]);
    e1.x = __expf(v1[0] - m[0]); e1.y = __expf(v1[1] - m[1]);
    e1.z = __expf(v1[2] - m[2]); e1.w = __expf(v1[3] - m[3]);
    es4[w * NLAB + lane]      = e0;
    es4[w * NLAB + lane + 32] = e1;
    __syncwarp();

    float aLo[4] = {0.f, 0.f, 0.f, 0.f}, aHi[4] = {0.f, 0.f, 0.f, 0.f};
#pragma unroll
    for (int k = 0; k < NLAB; k++) {
        float2 t = Ep[k * 32 + lane];      // {expT[lane][k], expT[lane+32][k]}
        float4 e = es4[w * NLAB + k];      // broadcast
        aLo[0] = fmaf(t.x, e.x, aLo[0]); aHi[0] = fmaf(t.y, e.x, aHi[0]);
        aLo[1] = fmaf(t.x, e.y, aLo[1]); aHi[1] = fmaf(t.y, e.y, aHi[1]);
        aLo[2] = fmaf(t.x, e.z, aLo[2]); aHi[2] = fmaf(t.y, e.z, aHi[2]);
        aLo[3] = fmaf(t.x, e.w, aLo[3]); aHi[3] = fmaf(t.y, e.w, aHi[3]);
    }

    float s0lo = m[0] + __logf(aLo[0]) + m[1] + __logf(aLo[1]);
    float s0hi = m[0] + __logf(aHi[0]) + m[1] + __logf(aHi[1]);

    const float* er0 = base + (size_t)g0 * NLAB;
    if (outp) {
        outp[b * NLAB + lane]      = er0[lane] + s0lo;
        outp[b * NLAB + lane + 32] = er0[lane + 32] + s0hi;
    } else {
        float* wr0 = base + (size_t)g0 * NLAB;
        float o0 = er0[lane] + s0lo;
        float o1 = er0[lane + 32] + s0hi;
        wr0[lane] = o0; wr0[lane + 32] = o1;
        if (n > 1) {
            float s1lo = m[2] + __logf(aLo[2]) + m[3] + __logf(aLo[3]);
            float s1hi = m[2] + __logf(aHi[2]) + m[3] + __logf(aHi[3]);
            const float* er1 = base + (size_t)(g0 + 1) * NLAB;
            float* wr1 = base + (size_t)(g0 + 1) * NLAB;
            float p0 = er1[lane] + s1lo;
            float p1 = er1[lane + 32] + s1hi;
            wr1[lane] = p0; wr1[lane + 32] = p1;
        }
    }
}

// ---------------------------------------------------------------------------
// Launcher
// ---------------------------------------------------------------------------
extern "C" void kernel_launch(void* const* d_in, const int* in_sizes, int n_in,
                              void* d_out, int out_size) {
    const float* hidden = (const float*)d_in[0];
    const float* W      = (const float*)d_in[1];
    const float* bias   = (const float*)d_in[2];
    const float* trans  = (const float*)d_in[3];
    float* out = (float*)d_out;

    init_expT_kernel<<<8, 256>>>(trans);
    init_Wbf_kernel<<<(DIN * NLAB + 255) / 256, 256>>>(W);
    gemm_kernel<<<NNODES, 256>>>(hidden, bias);

    for (int n = 512; n >= 1; n >>= 1) {
        int P = (n > 1) ? (n >> 1) : 1;
        int logP = 0;
        while ((1 << logP) < P) logP++;
        int blocks = (BATCH * P) / 8;
        tree_kernel<<<blocks, 256>>>(n, P, logP, (n == 1) ? out : nullptr);
    }
}

// round 4
// speedup vs baseline: 2.6062x; 1.8694x over previous
#include <cuda_runtime.h>
#include <cuda_bf16.h>
#include <cstdint>

#define BATCH   128
#define NNODES  2047
#define DIN     512
#define NLAB    64

// ---------------------------------------------------------------------------
// Scratch (device globals)
// ---------------------------------------------------------------------------
__device__ __nv_bfloat16 g_E[(size_t)BATCH * NNODES * NLAB]; // exp-form vectors u_g (34MB)
__device__ float         g_S[BATCH * NNODES];                // per-node shift contributions
__device__ float2        g_expT[NLAB * 32];                  // f32 pairs for tail: [k][j]={T'[j][k],T'[j+32][k]}
__device__ __nv_bfloat16 g_expTb[NLAB * NLAB];               // bf16 [k][l] = exp(trans[l][k])
__device__ __nv_bfloat16 g_Wbf[DIN * NLAB];                  // W bf16 [k][n]

// ---------------------------------------------------------------------------
// helpers
// ---------------------------------------------------------------------------
__device__ __forceinline__ uint32_t smem_u32(const void* p) {
    uint32_t a;
    asm("{ .reg .u64 t; cvta.to.shared.u64 t, %1; cvt.u32.u64 %0, t; }" : "=r"(a) : "l"(p));
    return a;
}
__device__ __forceinline__ void ldsm_x4(uint32_t* r, uint32_t addr) {
    asm volatile("ldmatrix.sync.aligned.m8n8.x4.shared.b16 {%0,%1,%2,%3}, [%4];"
                 : "=r"(r[0]), "=r"(r[1]), "=r"(r[2]), "=r"(r[3]) : "r"(addr));
}
__device__ __forceinline__ void ldsm_x4_t(uint32_t* r, uint32_t addr) {
    asm volatile("ldmatrix.sync.aligned.m8n8.x4.trans.shared.b16 {%0,%1,%2,%3}, [%4];"
                 : "=r"(r[0]), "=r"(r[1]), "=r"(r[2]), "=r"(r[3]) : "r"(addr));
}
__device__ __forceinline__ void mma_bf16(float* c, const uint32_t* a, const uint32_t* b) {
    asm volatile(
        "mma.sync.aligned.m16n8k16.row.col.f32.bf16.bf16.f32 "
        "{%0,%1,%2,%3}, {%4,%5,%6,%7}, {%8,%9}, {%0,%1,%2,%3};"
        : "+f"(c[0]), "+f"(c[1]), "+f"(c[2]), "+f"(c[3])
        : "r"(a[0]), "r"(a[1]), "r"(a[2]), "r"(a[3]), "r"(b[0]), "r"(b[1]));
}
__device__ __forceinline__ void cp16(uint32_t sa, const void* g) {
    asm volatile("cp.async.cg.shared.global [%0], [%1], 16;" :: "r"(sa), "l"(g));
}
__device__ __forceinline__ uint32_t packbf(float a, float b) {
    __nv_bfloat162 p = __floats2bfloat162_rn(a, b);
    uint32_t u; memcpy(&u, &p, 4);
    return u;
}

// ---------------------------------------------------------------------------
// Init kernels
// ---------------------------------------------------------------------------
__global__ void init_expT(const float* __restrict__ trans) {
    int idx = blockIdx.x * blockDim.x + threadIdx.x;
    if (idx < NLAB * 32) {
        int k = idx >> 5, j = idx & 31;
        g_expT[idx] = make_float2(expf(trans[j * NLAB + k]),
                                  expf(trans[(j + 32) * NLAB + k]));
    }
}
__global__ void init_expTb(const float* __restrict__ trans) {
    int idx = blockIdx.x * blockDim.x + threadIdx.x;
    if (idx < NLAB * NLAB) {
        int k = idx >> 6, l = idx & 63;
        g_expTb[idx] = __float2bfloat16(expf(trans[l * NLAB + k]));
    }
}
__global__ void init_Wbf(const float* __restrict__ W) {
    int idx = blockIdx.x * blockDim.x + threadIdx.x;
    if (idx < DIN * NLAB) g_Wbf[idx] = __float2bfloat16(W[idx]);
}

// ---------------------------------------------------------------------------
// GEMM: emis = hidden@W + b, then per-row a=max, E=exp(emis-a) bf16, g_S=a.
// CTA 128 rows x 64 cols, 8 warps each 16 rows x 64 cols.
// ---------------------------------------------------------------------------
#define ASTR 40
#define BSTR 72
#define NCH  16

__global__ __launch_bounds__(256)
void gemm_kernel(const float* __restrict__ A, const float* __restrict__ bias) {
    __shared__ __nv_bfloat16 As[2][128 * ASTR];
    __shared__ __nv_bfloat16 Ws[2][32 * BSTR];
    __shared__ float bs[NLAB];

    const int tid = threadIdx.x;
    if (tid < NLAB) bs[tid] = bias[tid];

    const int wm = tid >> 5, lane = tid & 31;
    const int grp = lane >> 2, tig = lane & 3;
    const size_t r0 = (size_t)blockIdx.x * 128;

    const int a_row = tid >> 3, a_c4 = tid & 7;
    const int w_row = tid >> 3, w_j = (tid & 7) * 2;
    const float4* Ag = (const float4*)(A + r0 * DIN);
    const uint2*  Wg = (const uint2*)g_Wbf;

    float acc[8][4] = {};
    float4 va[4];
    uint2  vw[2];

#define LOAD_REGS(c)                                                        \
    do {                                                                    \
        _Pragma("unroll")                                                   \
        for (int p = 0; p < 4; p++)                                         \
            va[p] = Ag[(size_t)(a_row + p * 32) * (DIN / 4) + (c) * 8 + a_c4]; \
        vw[0] = Wg[((c) * 32 + w_row) * 16 + w_j];                          \
        vw[1] = Wg[((c) * 32 + w_row) * 16 + w_j + 1];                      \
    } while (0)

#define STORE_SMEM(buf)                                                     \
    do {                                                                    \
        _Pragma("unroll")                                                   \
        for (int p = 0; p < 4; p++) {                                       \
            uint2 pk;                                                       \
            pk.x = packbf(va[p].x, va[p].y);                                \
            pk.y = packbf(va[p].z, va[p].w);                                \
            *(uint2*)&As[buf][(a_row + p * 32) * ASTR + a_c4 * 4] = pk;     \
        }                                                                   \
        *(uint2*)&Ws[buf][w_row * BSTR + w_j * 4]     = vw[0];              \
        *(uint2*)&Ws[buf][w_row * BSTR + w_j * 4 + 4] = vw[1];              \
    } while (0)

    LOAD_REGS(0);
    STORE_SMEM(0);
    __syncthreads();

#pragma unroll 2
    for (int c = 0; c < NCH; c++) {
        const int s = c & 1;
        if (c + 1 < NCH) LOAD_REGS(c + 1);

        const uint32_t as_b = smem_u32(&As[s][0]);
        const uint32_t ws_b = smem_u32(&Ws[s][0]);
#pragma unroll
        for (int kk = 0; kk < 2; kk++) {
            uint32_t a[4], bbv[4][4];
            ldsm_x4(a, as_b + (uint32_t)((wm * 16 + (lane & 15)) * ASTR
                                         + kk * 16 + ((lane >> 4) << 3)) * 2);
#pragma unroll
            for (int nt = 0; nt < 4; nt++)
                ldsm_x4_t(bbv[nt], ws_b + (uint32_t)((kk * 16 + (lane & 15)) * BSTR
                                                     + nt * 16 + ((lane >> 4) << 3)) * 2);
#pragma unroll
            for (int nt = 0; nt < 4; nt++) {
                mma_bf16(acc[nt * 2],     a, &bbv[nt][0]);
                mma_bf16(acc[nt * 2 + 1], a, &bbv[nt][2]);
            }
        }
        if (c + 1 < NCH) {
            STORE_SMEM((c + 1) & 1);
            __syncthreads();
        }
    }
#undef LOAD_REGS
#undef STORE_SMEM

    // Epilogue: +bias, row max, exp, bf16 store + g_S
    __syncthreads();   // protect smem reuse
    const int r0l = wm * 16 + grp;
    float v0[16], v1[16];
    float m0 = -1e30f, m1 = -1e30f;
#pragma unroll
    for (int nb = 0; nb < 8; nb++) {
#pragma unroll
        for (int h = 0; h < 2; h++) {
            int cc = nb * 8 + tig * 2 + h;
            float x0 = acc[nb][h]     + bs[cc];
            float x1 = acc[nb][2 + h] + bs[cc];
            v0[nb * 2 + h] = x0; v1[nb * 2 + h] = x1;
            m0 = fmaxf(m0, x0); m1 = fmaxf(m1, x1);
        }
    }
    m0 = fmaxf(m0, __shfl_xor_sync(0xffffffffu, m0, 1));
    m0 = fmaxf(m0, __shfl_xor_sync(0xffffffffu, m0, 2));
    m1 = fmaxf(m1, __shfl_xor_sync(0xffffffffu, m1, 1));
    m1 = fmaxf(m1, __shfl_xor_sync(0xffffffffu, m1, 2));

    __nv_bfloat16* stage = (__nv_bfloat16*)As;   // 128 x 72 staging
#pragma unroll
    for (int nb = 0; nb < 8; nb++) {
        *(uint32_t*)&stage[r0l * 72 + nb * 8 + tig * 2] =
            packbf(__expf(v0[nb * 2] - m0), __expf(v0[nb * 2 + 1] - m0));
        *(uint32_t*)&stage[(r0l + 8) * 72 + nb * 8 + tig * 2] =
            packbf(__expf(v1[nb * 2] - m1), __expf(v1[nb * 2 + 1] - m1));
    }
    if (tig == 0) { g_S[r0 + r0l] = m0; g_S[r0 + r0l + 8] = m1; }
    __syncwarp();
#pragma unroll
    for (int p = 0; p < 4; p++) {
        int q = lane + 32 * p;
        int rr = q >> 3, c16 = q & 7;
        uint4 d = *(uint4*)&stage[(wm * 16 + rr) * 72 + c16 * 8];
        *(uint4*)&g_E[(r0 + wm * 16 + rr) * 64 + c16 * 8] = d;
    }
}

// ---------------------------------------------------------------------------
// Tree level (n >= 64): CTA = 64 parents (128 children). tensor-core matvec.
// S = children @ expT^T; q = E_parent * S_L * S_R; u = q/maxq; g_S += log maxq.
// ---------------------------------------------------------------------------
__global__ __launch_bounds__(256)
void tree_big(int n, int cpb) {
    __shared__ __nv_bfloat16 At[128 * 72];
    __shared__ __nv_bfloat16 Bt[64 * 72];

    const int tid = threadIdx.x;
    const int wm = tid >> 5, lane = tid & 31;
    const int grp = lane >> 2, tig = lane & 3;
    const int b = blockIdx.x / cpb, j = blockIdx.x % cpb;
    const int g0 = n - 1 + 64 * j;
    const size_t prow0 = (size_t)b * NNODES + g0;
    const size_t crow0 = (size_t)b * NNODES + 2 * g0 + 1;

    const uint32_t at_b = smem_u32(At), bt_b = smem_u32(Bt);
    const char* Cg = (const char*)(g_E + crow0 * 64);
    for (int q = tid; q < 1024; q += 256) {
        int r = q >> 3, c = q & 7;
        cp16(at_b + (uint32_t)(r * 72 + c * 8) * 2, Cg + q * 16);
    }
    const char* Tg = (const char*)g_expTb;
    for (int q = tid; q < 512; q += 256) {
        int r = q >> 3, c = q & 7;
        cp16(bt_b + (uint32_t)(r * 72 + c * 8) * 2, Tg + q * 16);
    }
    asm volatile("cp.async.commit_group;");
    asm volatile("cp.async.wait_group 0;");
    __syncthreads();

    float acc[8][4] = {};
#pragma unroll
    for (int kk = 0; kk < 4; kk++) {
        uint32_t a[4], bbv[4][4];
        ldsm_x4(a, at_b + (uint32_t)((wm * 16 + (lane & 15)) * 72
                                     + kk * 16 + ((lane >> 4) << 3)) * 2);
#pragma unroll
        for (int nt = 0; nt < 4; nt++)
            ldsm_x4_t(bbv[nt], bt_b + (uint32_t)((kk * 16 + (lane & 15)) * 72
                                                 + nt * 16 + ((lane >> 4) << 3)) * 2);
#pragma unroll
        for (int nt = 0; nt < 4; nt++) {
            mma_bf16(acc[nt * 2],     a, &bbv[nt][0]);
            mma_bf16(acc[nt * 2 + 1], a, &bbv[nt][2]);
        }
    }

    // Epilogue
    const int r0l = wm * 16 + grp;
    const size_t pg0 = prow0 + (r0l >> 1);
    const size_t pg1 = prow0 + ((r0l + 8) >> 1);

    float q0[16], q1[16];
    float C0 = 0.f, C1 = 0.f;
#pragma unroll
    for (int nb = 0; nb < 8; nb++) {
        uint32_t e0u = *(const uint32_t*)&g_E[pg0 * 64 + nb * 8 + tig * 2];
        uint32_t e1u = *(const uint32_t*)&g_E[pg1 * 64 + nb * 8 + tig * 2];
        __nv_bfloat162 e0b, e1b;
        memcpy(&e0b, &e0u, 4); memcpy(&e1b, &e1u, 4);
        float s00 = acc[nb][0], s01 = acc[nb][1];
        float s10 = acc[nb][2], s11 = acc[nb][3];
        float p00 = s00 * __shfl_xor_sync(0xffffffffu, s00, 4);
        float p01 = s01 * __shfl_xor_sync(0xffffffffu, s01, 4);
        float p10 = s10 * __shfl_xor_sync(0xffffffffu, s10, 4);
        float p11 = s11 * __shfl_xor_sync(0xffffffffu, s11, 4);
        q0[nb * 2]     = __bfloat162float(e0b.x) * p00;
        q0[nb * 2 + 1] = __bfloat162float(e0b.y) * p01;
        q1[nb * 2]     = __bfloat162float(e1b.x) * p10;
        q1[nb * 2 + 1] = __bfloat162float(e1b.y) * p11;
        C0 = fmaxf(C0, fmaxf(q0[nb * 2], q0[nb * 2 + 1]));
        C1 = fmaxf(C1, fmaxf(q1[nb * 2], q1[nb * 2 + 1]));
    }
    C0 = fmaxf(C0, __shfl_xor_sync(0xffffffffu, C0, 1));
    C0 = fmaxf(C0, __shfl_xor_sync(0xffffffffu, C0, 2));
    C1 = fmaxf(C1, __shfl_xor_sync(0xffffffffu, C1, 1));
    C1 = fmaxf(C1, __shfl_xor_sync(0xffffffffu, C1, 2));
    float i0 = __fdividef(1.0f, C0), i1 = __fdividef(1.0f, C1);

    if (!(grp & 1)) {
#pragma unroll
        for (int nb = 0; nb < 8; nb++) {
            *(uint32_t*)&g_E[pg0 * 64 + nb * 8 + tig * 2] =
                packbf(q0[nb * 2] * i0, q0[nb * 2 + 1] * i0);
            *(uint32_t*)&g_E[pg1 * 64 + nb * 8 + tig * 2] =
                packbf(q1[nb * 2] * i1, q1[nb * 2 + 1] * i1);
        }
        if (tig == 0) {
            g_S[pg0] += __logf(C0);
            g_S[pg1] += __logf(C1);
        }
    }
}

// ---------------------------------------------------------------------------
// Tail: one CTA per batch. Levels n=32..1 in smem + global shift sum + output.
// ---------------------------------------------------------------------------
__global__ __launch_bounds__(256)
void tail_kernel(float* __restrict__ out) {
    __shared__ float  Eb[127 * 64];     // f32 node vectors, nodes 0..126
    __shared__ float2 Ept[NLAB * 32];
    __shared__ float  warpS[8];
    __shared__ float  sGlob;

    const int tid = threadIdx.x;
    const int wm = tid >> 5, lane = tid & 31;
    const int b = blockIdx.x;

    for (int i = tid; i < NLAB * 32; i += 256) Ept[i] = g_expT[i];
    const uint32_t* src = (const uint32_t*)(g_E + (size_t)b * NNODES * 64);
    for (int i = tid; i < 4064; i += 256) {
        uint32_t v = src[i];
        __nv_bfloat162 bb; memcpy(&bb, &v, 4);
        Eb[2 * i]     = __bfloat162float(bb.x);
        Eb[2 * i + 1] = __bfloat162float(bb.y);
    }
    float s = 0.f;
    const float* Sb = g_S + (size_t)b * NNODES;
    for (int i = tid; i < NNODES; i += 256) s += Sb[i];
#pragma unroll
    for (int o = 16; o > 0; o >>= 1) s += __shfl_xor_sync(0xffffffffu, s, o);
    if (lane == 0) warpS[wm] = s;
    __syncthreads();
    if (tid == 0) {
        float t = 0.f;
        for (int i = 0; i < 8; i++) t += warpS[i];
        sGlob = t;
    }
    __syncthreads();

    float wlog = 0.f;
    for (int n = 32; n >= 2; n >>= 1) {
        for (int i = wm; i < n; i += 8) {
            int p = n - 1 + i, cL = 2 * p + 1, cR = cL + 1;
            float aL0 = 0.f, aL1 = 0.f, aR0 = 0.f, aR1 = 0.f;
#pragma unroll
            for (int k = 0; k < NLAB; k++) {
                float2 t = Ept[k * 32 + lane];
                float uL = Eb[cL * 64 + k], uR = Eb[cR * 64 + k];
                aL0 = fmaf(t.x, uL, aL0); aL1 = fmaf(t.y, uL, aL1);
                aR0 = fmaf(t.x, uR, aR0); aR1 = fmaf(t.y, uR, aR1);
            }
            float q0 = Eb[p * 64 + lane]      * aL0 * aR0;
            float q1 = Eb[p * 64 + lane + 32] * aL1 * aR1;
            float C = fmaxf(q0, q1);
#pragma unroll
            for (int o = 16; o > 0; o >>= 1) C = fmaxf(C, __shfl_xor_sync(0xffffffffu, C, o));
            float inv = __fdividef(1.0f, C);
            Eb[p * 64 + lane]      = q0 * inv;
            Eb[p * 64 + lane + 32] = q1 * inv;
            wlog += __logf(C);
        }
        __syncthreads();
    }
    if (lane == 0) warpS[wm] = wlog;
    __syncthreads();

    if (wm == 0) {
        float S = sGlob;
#pragma unroll
        for (int i = 0; i < 8; i++) S += warpS[i];
        // root: p=0, children 1,2
        float aL0 = 0.f, aL1 = 0.f, aR0 = 0.f, aR1 = 0.f;
#pragma unroll
        for (int k = 0; k < NLAB; k++) {
            float2 t = Ept[k * 32 + lane];
            float uL = Eb[64 + k], uR = Eb[128 + k];
            aL0 = fmaf(t.x, uL, aL0); aL1 = fmaf(t.y, uL, aL1);
            aR0 = fmaf(t.x, uR, aR0); aR1 = fmaf(t.y, uR, aR1);
        }
        float q0 = Eb[lane]      * aL0 * aR0;
        float q1 = Eb[lane + 32] * aL1 * aR1;
        out[b * NLAB + lane]      = S + __logf(q0);
        out[b * NLAB + lane + 32] = S + __logf(q1);
    }
}

// ---------------------------------------------------------------------------
// Launcher
// ---------------------------------------------------------------------------
extern "C" void kernel_launch(void* const* d_in, const int* in_sizes, int n_in,
                              void* d_out, int out_size) {
    const float* hidden = (const float*)d_in[0];
    const float* W      = (const float*)d_in[1];
    const float* bias   = (const float*)d_in[2];
    const float* trans  = (const float*)d_in[3];
    float* out = (float*)d_out;

    init_expT<<<8, 256>>>(trans);
    init_expTb<<<16, 256>>>(trans);
    init_Wbf<<<128, 256>>>(W);
    gemm_kernel<<<NNODES, 256>>>(hidden, bias);

    tree_big<<<1024, 256>>>(512, 8);
    tree_big<<<512, 256>>>(256, 4);
    tree_big<<<256, 256>>>(128, 2);
    tree_big<<<128, 256>>>(64, 1);

    tail_kernel<<<BATCH, 256>>>(out);
}

// round 5
// speedup vs baseline: 2.9293x; 1.1240x over previous
#include <cuda_runtime.h>
#include <cuda_bf16.h>
#include <cstdint>

#define BATCH   128
#define NNODES  2047
#define DIN     512
#define NLAB    64

// ---------------------------------------------------------------------------
// Scratch (device globals)
// ---------------------------------------------------------------------------
__device__ __nv_bfloat16 g_E[(size_t)BATCH * NNODES * NLAB]; // exp-form vectors u_g (34MB)
__device__ float         g_S[BATCH * NNODES];                // per-node shift contributions
__device__ float2        g_expT[NLAB * 32];                  // f32 pairs for tail
__device__ __nv_bfloat16 g_expTb[NLAB * NLAB];               // bf16 [k][l] = exp(trans[l][k])
__device__ __nv_bfloat16 g_Wbf[DIN * NLAB];                  // W bf16 [k][n]

// ---------------------------------------------------------------------------
// helpers
// ---------------------------------------------------------------------------
__device__ __forceinline__ uint32_t smem_u32(const void* p) {
    uint32_t a;
    asm("{ .reg .u64 t; cvta.to.shared.u64 t, %1; cvt.u32.u64 %0, t; }" : "=r"(a) : "l"(p));
    return a;
}
__device__ __forceinline__ void ldsm_x4(uint32_t* r, uint32_t addr) {
    asm volatile("ldmatrix.sync.aligned.m8n8.x4.shared.b16 {%0,%1,%2,%3}, [%4];"
                 : "=r"(r[0]), "=r"(r[1]), "=r"(r[2]), "=r"(r[3]) : "r"(addr));
}
__device__ __forceinline__ void ldsm_x4_t(uint32_t* r, uint32_t addr) {
    asm volatile("ldmatrix.sync.aligned.m8n8.x4.trans.shared.b16 {%0,%1,%2,%3}, [%4];"
                 : "=r"(r[0]), "=r"(r[1]), "=r"(r[2]), "=r"(r[3]) : "r"(addr));
}
__device__ __forceinline__ void mma_bf16(float* c, const uint32_t* a, const uint32_t* b) {
    asm volatile(
        "mma.sync.aligned.m16n8k16.row.col.f32.bf16.bf16.f32 "
        "{%0,%1,%2,%3}, {%4,%5,%6,%7}, {%8,%9}, {%0,%1,%2,%3};"
        : "+f"(c[0]), "+f"(c[1]), "+f"(c[2]), "+f"(c[3])
        : "r"(a[0]), "r"(a[1]), "r"(a[2]), "r"(a[3]), "r"(b[0]), "r"(b[1]));
}
__device__ __forceinline__ void cp16(uint32_t sa, const void* g) {
    asm volatile("cp.async.cg.shared.global [%0], [%1], 16;" :: "r"(sa), "l"(g));
}
__device__ __forceinline__ uint32_t packbf(float a, float b) {
    __nv_bfloat162 p = __floats2bfloat162_rn(a, b);
    uint32_t u; memcpy(&u, &p, 4);
    return u;
}

// ---------------------------------------------------------------------------
// Init kernels
// ---------------------------------------------------------------------------
__global__ void init_expT(const float* __restrict__ trans) {
    int idx = blockIdx.x * blockDim.x + threadIdx.x;
    if (idx < NLAB * 32) {
        int k = idx >> 5, j = idx & 31;
        g_expT[idx] = make_float2(expf(trans[j * NLAB + k]),
                                  expf(trans[(j + 32) * NLAB + k]));
    }
}
__global__ void init_expTb(const float* __restrict__ trans) {
    int idx = blockIdx.x * blockDim.x + threadIdx.x;
    if (idx < NLAB * NLAB) {
        int k = idx >> 6, l = idx & 63;
        g_expTb[idx] = __float2bfloat16(expf(trans[l * NLAB + k]));
    }
}
__global__ void init_Wbf(const float* __restrict__ W) {
    int idx = blockIdx.x * blockDim.x + threadIdx.x;
    if (idx < DIN * NLAB) g_Wbf[idx] = __float2bfloat16(W[idx]);
}

// ---------------------------------------------------------------------------
// GEMM: emis = hidden@W + b, then per-row a=max, E=exp(emis-a) bf16, g_S=a.
// (unchanged from Round 4)
// ---------------------------------------------------------------------------
#define ASTR 40
#define BSTR 72
#define NCH  16

__global__ __launch_bounds__(256)
void gemm_kernel(const float* __restrict__ A, const float* __restrict__ bias) {
    __shared__ __nv_bfloat16 As[2][128 * ASTR];
    __shared__ __nv_bfloat16 Ws[2][32 * BSTR];
    __shared__ float bs[NLAB];

    const int tid = threadIdx.x;
    if (tid < NLAB) bs[tid] = bias[tid];

    const int wm = tid >> 5, lane = tid & 31;
    const int grp = lane >> 2, tig = lane & 3;
    const size_t r0 = (size_t)blockIdx.x * 128;

    const int a_row = tid >> 3, a_c4 = tid & 7;
    const int w_row = tid >> 3, w_j = (tid & 7) * 2;
    const float4* Ag = (const float4*)(A + r0 * DIN);
    const uint2*  Wg = (const uint2*)g_Wbf;

    float acc[8][4] = {};
    float4 va[4];
    uint2  vw[2];

#define LOAD_REGS(c)                                                        \
    do {                                                                    \
        _Pragma("unroll")                                                   \
        for (int p = 0; p < 4; p++)                                         \
            va[p] = Ag[(size_t)(a_row + p * 32) * (DIN / 4) + (c) * 8 + a_c4]; \
        vw[0] = Wg[((c) * 32 + w_row) * 16 + w_j];                          \
        vw[1] = Wg[((c) * 32 + w_row) * 16 + w_j + 1];                      \
    } while (0)

#define STORE_SMEM(buf)                                                     \
    do {                                                                    \
        _Pragma("unroll")                                                   \
        for (int p = 0; p < 4; p++) {                                       \
            uint2 pk;                                                       \
            pk.x = packbf(va[p].x, va[p].y);                                \
            pk.y = packbf(va[p].z, va[p].w);                                \
            *(uint2*)&As[buf][(a_row + p * 32) * ASTR + a_c4 * 4] = pk;     \
        }                                                                   \
        *(uint2*)&Ws[buf][w_row * BSTR + w_j * 4]     = vw[0];              \
        *(uint2*)&Ws[buf][w_row * BSTR + w_j * 4 + 4] = vw[1];              \
    } while (0)

    LOAD_REGS(0);
    STORE_SMEM(0);
    __syncthreads();

#pragma unroll 2
    for (int c = 0; c < NCH; c++) {
        const int s = c & 1;
        if (c + 1 < NCH) LOAD_REGS(c + 1);

        const uint32_t as_b = smem_u32(&As[s][0]);
        const uint32_t ws_b = smem_u32(&Ws[s][0]);
#pragma unroll
        for (int kk = 0; kk < 2; kk++) {
            uint32_t a[4], bbv[4][4];
            ldsm_x4(a, as_b + (uint32_t)((wm * 16 + (lane & 15)) * ASTR
                                         + kk * 16 + ((lane >> 4) << 3)) * 2);
#pragma unroll
            for (int nt = 0; nt < 4; nt++)
                ldsm_x4_t(bbv[nt], ws_b + (uint32_t)((kk * 16 + (lane & 15)) * BSTR
                                                     + nt * 16 + ((lane >> 4) << 3)) * 2);
#pragma unroll
            for (int nt = 0; nt < 4; nt++) {
                mma_bf16(acc[nt * 2],     a, &bbv[nt][0]);
                mma_bf16(acc[nt * 2 + 1], a, &bbv[nt][2]);
            }
        }
        if (c + 1 < NCH) {
            STORE_SMEM((c + 1) & 1);
            __syncthreads();
        }
    }
#undef LOAD_REGS
#undef STORE_SMEM

    __syncthreads();
    const int r0l = wm * 16 + grp;
    float v0[16], v1[16];
    float m0 = -1e30f, m1 = -1e30f;
#pragma unroll
    for (int nb = 0; nb < 8; nb++) {
#pragma unroll
        for (int h = 0; h < 2; h++) {
            int cc = nb * 8 + tig * 2 + h;
            float x0 = acc[nb][h]     + bs[cc];
            float x1 = acc[nb][2 + h] + bs[cc];
            v0[nb * 2 + h] = x0; v1[nb * 2 + h] = x1;
            m0 = fmaxf(m0, x0); m1 = fmaxf(m1, x1);
        }
    }
    m0 = fmaxf(m0, __shfl_xor_sync(0xffffffffu, m0, 1));
    m0 = fmaxf(m0, __shfl_xor_sync(0xffffffffu, m0, 2));
    m1 = fmaxf(m1, __shfl_xor_sync(0xffffffffu, m1, 1));
    m1 = fmaxf(m1, __shfl_xor_sync(0xffffffffu, m1, 2));

    __nv_bfloat16* stage = (__nv_bfloat16*)As;
#pragma unroll
    for (int nb = 0; nb < 8; nb++) {
        *(uint32_t*)&stage[r0l * 72 + nb * 8 + tig * 2] =
            packbf(__expf(v0[nb * 2] - m0), __expf(v0[nb * 2 + 1] - m0));
        *(uint32_t*)&stage[(r0l + 8) * 72 + nb * 8 + tig * 2] =
            packbf(__expf(v1[nb * 2] - m1), __expf(v1[nb * 2 + 1] - m1));
    }
    if (tig == 0) { g_S[r0 + r0l] = m0; g_S[r0 + r0l + 8] = m1; }
    __syncwarp();
#pragma unroll
    for (int p = 0; p < 4; p++) {
        int q = lane + 32 * p;
        int rr = q >> 3, c16 = q & 7;
        uint4 d = *(uint4*)&stage[(wm * 16 + rr) * 72 + c16 * 8];
        *(uint4*)&g_E[(r0 + wm * 16 + rr) * 64 + c16 * 8] = d;
    }
}

// ---------------------------------------------------------------------------
// Subtree kernel: CTA = (batch b, subtree j of 8).  Loads 128 leaves, reduces
// 7 levels (P=64..1) entirely in smem, writes node (7+j) + accumulated shift.
// Parent-emission rows staged via cp.async overlapped with the level's MMA.
// ---------------------------------------------------------------------------
__global__ __launch_bounds__(256)
void subtree_kernel() {
    __shared__ __nv_bfloat16 Cur[128 * 72];   // children/level values (ldsm layout)
    __shared__ __nv_bfloat16 Tb[64 * 72];     // expTb (ldsm layout)
    __shared__ __nv_bfloat16 Par[64 * 64];    // parent emission rows (linear)
    __shared__ float warpS[8];

    const int tid = threadIdx.x;
    const int wm = tid >> 5, lane = tid & 31;
    const int grp = lane >> 2, tig = lane & 3;
    const int b = blockIdx.x >> 3, j = blockIdx.x & 7;
    const size_t nb_base = (size_t)b * NNODES;

    const uint32_t cur_b = smem_u32(Cur), tb_b = smem_u32(Tb);
    const uint32_t par_b = smem_u32(Par);

    // load 128 leaf rows (contiguous 16KB) + expTb (8KB)
    const char* Lg = (const char*)(g_E + (nb_base + 1023 + 128 * j) * 64);
    for (int q = tid; q < 1024; q += 256) {
        int r = q >> 3, c = q & 7;
        cp16(cur_b + (uint32_t)(r * 72 + c * 8) * 2, Lg + q * 16);
    }
    const char* Tg = (const char*)g_expTb;
    for (int q = tid; q < 512; q += 256) {
        int r = q >> 3, c = q & 7;
        cp16(tb_b + (uint32_t)(r * 72 + c * 8) * 2, Tg + q * 16);
    }
    asm volatile("cp.async.commit_group;");
    asm volatile("cp.async.wait_group 0;");
    __syncthreads();

    float lsum = 0.f;

#pragma unroll 1
    for (int P = 64; P >= 1; P >>= 1) {
        const int nbase = 8 * P - 1 + P * j;     // parent node base in tree
        const int active = (wm * 16) < 2 * P;

        // stage parent emission rows (P x 128B contiguous) during MMA
        {
            const char* Pg = (const char*)(g_E + (nb_base + nbase) * 64);
            for (int q = tid; q < P * 8; q += 256)
                cp16(par_b + (uint32_t)(q * 16), Pg + q * 16);
            asm volatile("cp.async.commit_group;");
        }

        float acc[8][4];
#pragma unroll
        for (int nb = 0; nb < 8; nb++)
#pragma unroll
            for (int i = 0; i < 4; i++) acc[nb][i] = 0.f;

        if (active) {
#pragma unroll
            for (int kk = 0; kk < 4; kk++) {
                uint32_t a[4], bbv[4][4];
                ldsm_x4(a, cur_b + (uint32_t)((wm * 16 + (lane & 15)) * 72
                                              + kk * 16 + ((lane >> 4) << 3)) * 2);
#pragma unroll
                for (int nt = 0; nt < 4; nt++)
                    ldsm_x4_t(bbv[nt], tb_b + (uint32_t)((kk * 16 + (lane & 15)) * 72
                                                         + nt * 16 + ((lane >> 4) << 3)) * 2);
#pragma unroll
                for (int nt = 0; nt < 4; nt++) {
                    mma_bf16(acc[nt * 2],     a, &bbv[nt][0]);
                    mma_bf16(acc[nt * 2 + 1], a, &bbv[nt][2]);
                }
            }
        }
        asm volatile("cp.async.wait_group 0;");
        __syncthreads();   // all Cur reads done; Par staged

        if (active) {
            const int p0 = wm * 8 + (grp >> 1);
            const int p1 = p0 + 4;
            const bool ok0 = p0 < P, ok1 = p1 < P;

            float q0[16], q1[16];
            float C0 = 0.f, C1 = 0.f;
#pragma unroll
            for (int nb = 0; nb < 8; nb++) {
                float s00 = acc[nb][0], s01 = acc[nb][1];
                float s10 = acc[nb][2], s11 = acc[nb][3];
                float p00 = s00 * __shfl_xor_sync(0xffffffffu, s00, 4);
                float p01 = s01 * __shfl_xor_sync(0xffffffffu, s01, 4);
                float p10 = s10 * __shfl_xor_sync(0xffffffffu, s10, 4);
                float p11 = s11 * __shfl_xor_sync(0xffffffffu, s11, 4);
                uint32_t e0u = ok0 ? *(const uint32_t*)&Par[p0 * 64 + nb * 8 + tig * 2] : 0u;
                uint32_t e1u = ok1 ? *(const uint32_t*)&Par[p1 * 64 + nb * 8 + tig * 2] : 0u;
                __nv_bfloat162 e0b, e1b;
                memcpy(&e0b, &e0u, 4); memcpy(&e1b, &e1u, 4);
                q0[nb * 2]     = __bfloat162float(e0b.x) * p00;
                q0[nb * 2 + 1] = __bfloat162float(e0b.y) * p01;
                q1[nb * 2]     = __bfloat162float(e1b.x) * p10;
                q1[nb * 2 + 1] = __bfloat162float(e1b.y) * p11;
                C0 = fmaxf(C0, fmaxf(q0[nb * 2], q0[nb * 2 + 1]));
                C1 = fmaxf(C1, fmaxf(q1[nb * 2], q1[nb * 2 + 1]));
            }
            C0 = fmaxf(C0, __shfl_xor_sync(0xffffffffu, C0, 1));
            C0 = fmaxf(C0, __shfl_xor_sync(0xffffffffu, C0, 2));
            C1 = fmaxf(C1, __shfl_xor_sync(0xffffffffu, C1, 1));
            C1 = fmaxf(C1, __shfl_xor_sync(0xffffffffu, C1, 2));
            float i0 = __fdividef(1.0f, C0), i1 = __fdividef(1.0f, C1);

            if (!(grp & 1)) {
                if (ok0) {
#pragma unroll
                    for (int nb = 0; nb < 8; nb++)
                        *(uint32_t*)&Cur[p0 * 72 + nb * 8 + tig * 2] =
                            packbf(q0[nb * 2] * i0, q0[nb * 2 + 1] * i0);
                }
                if (ok1) {
#pragma unroll
                    for (int nb = 0; nb < 8; nb++)
                        *(uint32_t*)&Cur[p1 * 72 + nb * 8 + tig * 2] =
                            packbf(q1[nb * 2] * i1, q1[nb * 2 + 1] * i1);
                }
                if (tig == 0) {
                    if (ok0) lsum += __logf(C0);
                    if (ok1) lsum += __logf(C1);
                }
            }
        }
        __syncthreads();   // new level values visible
    }

    // Cur row 0 = node (7+j).  Write it + accumulated shift.
    if (tid < 8)
        *(uint4*)&g_E[(nb_base + 7 + j) * 64 + tid * 8] = *(uint4*)&Cur[tid * 8];

#pragma unroll
    for (int o = 16; o > 0; o >>= 1) lsum += __shfl_xor_sync(0xffffffffu, lsum, o);
    if (lane == 0) warpS[wm] = lsum;
    __syncthreads();
    if (tid == 0) {
        float t = 0.f;
        for (int i = 0; i < 8; i++) t += warpS[i];
        g_S[nb_base + 7 + j] += t;
    }
}

// ---------------------------------------------------------------------------
// Tail: one CTA per batch. g_S sum + levels over nodes 0..14 + root output.
// ---------------------------------------------------------------------------
__global__ __launch_bounds__(256)
void tail_kernel(float* __restrict__ out) {
    __shared__ float  Eb[15 * 64];
    __shared__ float2 Ept[NLAB * 32];
    __shared__ float  warpS[8];
    __shared__ float  sGlob;

    const int tid = threadIdx.x;
    const int wm = tid >> 5, lane = tid & 31;
    const int b = blockIdx.x;

    for (int i = tid; i < NLAB * 32; i += 256) Ept[i] = g_expT[i];
    const uint32_t* src = (const uint32_t*)(g_E + (size_t)b * NNODES * 64);
    for (int i = tid; i < 480; i += 256) {
        uint32_t v = src[i];
        __nv_bfloat162 bb; memcpy(&bb, &v, 4);
        Eb[2 * i]     = __bfloat162float(bb.x);
        Eb[2 * i + 1] = __bfloat162float(bb.y);
    }
    float s = 0.f;
    const float* Sb = g_S + (size_t)b * NNODES;
    for (int i = tid; i < NNODES; i += 256) s += Sb[i];
#pragma unroll
    for (int o = 16; o > 0; o >>= 1) s += __shfl_xor_sync(0xffffffffu, s, o);
    if (lane == 0) warpS[wm] = s;
    __syncthreads();
    if (tid == 0) {
        float t = 0.f;
        for (int i = 0; i < 8; i++) t += warpS[i];
        sGlob = t;
    }
    __syncthreads();

    if (wm == 0) {
        float wlog = 0.f;
        const int nodes[6] = {3, 4, 5, 6, 1, 2};
#pragma unroll 1
        for (int t = 0; t < 6; t++) {
            int p = nodes[t], cL = 2 * p + 1, cR = 2 * p + 2;
            float aL0 = 0.f, aL1 = 0.f, aR0 = 0.f, aR1 = 0.f;
#pragma unroll
            for (int k = 0; k < NLAB; k++) {
                float2 tt = Ept[k * 32 + lane];
                float uL = Eb[cL * 64 + k], uR = Eb[cR * 64 + k];
                aL0 = fmaf(tt.x, uL, aL0); aL1 = fmaf(tt.y, uL, aL1);
                aR0 = fmaf(tt.x, uR, aR0); aR1 = fmaf(tt.y, uR, aR1);
            }
            float q0 = Eb[p * 64 + lane]      * aL0 * aR0;
            float q1 = Eb[p * 64 + lane + 32] * aL1 * aR1;
            float C = fmaxf(q0, q1);
#pragma unroll
            for (int o = 16; o > 0; o >>= 1) C = fmaxf(C, __shfl_xor_sync(0xffffffffu, C, o));
            float inv = __fdividef(1.0f, C);
            Eb[p * 64 + lane]      = q0 * inv;
            Eb[p * 64 + lane + 32] = q1 * inv;
            wlog += __logf(C);
            __syncwarp();
        }
        // root: children 1, 2
        float aL0 = 0.f, aL1 = 0.f, aR0 = 0.f, aR1 = 0.f;
#pragma unroll
        for (int k = 0; k < NLAB; k++) {
            float2 tt = Ept[k * 32 + lane];
            float uL = Eb[64 + k], uR = Eb[128 + k];
            aL0 = fmaf(tt.x, uL, aL0); aL1 = fmaf(tt.y, uL, aL1);
            aR0 = fmaf(tt.x, uR, aR0); aR1 = fmaf(tt.y, uR, aR1);
        }
        float q0 = Eb[lane]      * aL0 * aR0;
        float q1 = Eb[lane + 32] * aL1 * aR1;
        float S = sGlob + wlog;
        out[b * NLAB + lane]      = S + __logf(q0);
        out[b * NLAB + lane + 32] = S + __logf(q1);
    }
}

// ---------------------------------------------------------------------------
// Launcher
// ---------------------------------------------------------------------------
extern "C" void kernel_launch(void* const* d_in, const int* in_sizes, int n_in,
                              void* d_out, int out_size) {
    const float* hidden = (const float*)d_in[0];
    const float* W      = (const float*)d_in[1];
    const float* bias   = (const float*)d_in[2];
    const float* trans  = (const float*)d_in[3];
    float* out = (float*)d_out;

    init_expT<<<8, 256>>>(trans);
    init_expTb<<<16, 256>>>(trans);
    init_Wbf<<<128, 256>>>(W);
    gemm_kernel<<<NNODES, 256>>>(hidden, bias);
    subtree_kernel<<<BATCH * 8, 256>>>();
    tail_kernel<<<BATCH, 256>>>(out);
}

// round 6
// speedup vs baseline: 3.2908x; 1.1234x over previous
#include <cuda_runtime.h>
#include <cuda_bf16.h>
#include <cstdint>

#define BATCH   128
#define NNODES  2047
#define DIN     512
#define NLAB    64

// ---------------------------------------------------------------------------
// Scratch (device globals)
// ---------------------------------------------------------------------------
__device__ __nv_bfloat16 g_E[(size_t)BATCH * NNODES * NLAB]; // exp-form vectors u_g (34MB)
__device__ float         g_S[BATCH * NNODES];                // per-node shift contributions
__device__ float2        g_expT[NLAB * 32];                  // f32 pairs for tail
__device__ __nv_bfloat16 g_expTb[NLAB * NLAB];               // bf16 [k][l] = exp(trans[l][k])
__device__ __nv_bfloat16 g_Wbf[DIN * NLAB];                  // W bf16 [k][n]

// ---------------------------------------------------------------------------
// helpers
// ---------------------------------------------------------------------------
__device__ __forceinline__ uint32_t smem_u32(const void* p) {
    uint32_t a;
    asm("{ .reg .u64 t; cvta.to.shared.u64 t, %1; cvt.u32.u64 %0, t; }" : "=r"(a) : "l"(p));
    return a;
}
__device__ __forceinline__ void ldsm_x4(uint32_t* r, uint32_t addr) {
    asm volatile("ldmatrix.sync.aligned.m8n8.x4.shared.b16 {%0,%1,%2,%3}, [%4];"
                 : "=r"(r[0]), "=r"(r[1]), "=r"(r[2]), "=r"(r[3]) : "r"(addr));
}
__device__ __forceinline__ void ldsm_x4_t(uint32_t* r, uint32_t addr) {
    asm volatile("ldmatrix.sync.aligned.m8n8.x4.trans.shared.b16 {%0,%1,%2,%3}, [%4];"
                 : "=r"(r[0]), "=r"(r[1]), "=r"(r[2]), "=r"(r[3]) : "r"(addr));
}
__device__ __forceinline__ void mma_bf16(float* c, const uint32_t* a, const uint32_t* b) {
    asm volatile(
        "mma.sync.aligned.m16n8k16.row.col.f32.bf16.bf16.f32 "
        "{%0,%1,%2,%3}, {%4,%5,%6,%7}, {%8,%9}, {%0,%1,%2,%3};"
        : "+f"(c[0]), "+f"(c[1]), "+f"(c[2]), "+f"(c[3])
        : "r"(a[0]), "r"(a[1]), "r"(a[2]), "r"(a[3]), "r"(b[0]), "r"(b[1]));
}
__device__ __forceinline__ void cp16(uint32_t sa, const void* g) {
    asm volatile("cp.async.cg.shared.global [%0], [%1], 16;" :: "r"(sa), "l"(g));
}
__device__ __forceinline__ uint32_t packbf(float a, float b) {
    __nv_bfloat162 p = __floats2bfloat162_rn(a, b);
    uint32_t u; memcpy(&u, &p, 4);
    return u;
}

// ---------------------------------------------------------------------------
// Fused init: expT (2048), expTb (4096), Wbf (32768) — one launch
// ---------------------------------------------------------------------------
__global__ void init_all(const float* __restrict__ trans, const float* __restrict__ W) {
    int idx = blockIdx.x * blockDim.x + threadIdx.x;
    if (idx < DIN * NLAB) g_Wbf[idx] = __float2bfloat16(W[idx]);
    if (idx < NLAB * 32) {
        int k = idx >> 5, j = idx & 31;
        g_expT[idx] = make_float2(expf(trans[j * NLAB + k]),
                                  expf(trans[(j + 32) * NLAB + k]));
    }
    if (idx < NLAB * NLAB) {
        int k = idx >> 6, l = idx & 63;
        g_expTb[idx] = __float2bfloat16(expf(trans[l * NLAB + k]));
    }
}

// ---------------------------------------------------------------------------
// GEMM: emis = hidden@W + b; per-row a=max, E=exp(emis-a) bf16, g_S=a.
// 4-stage cp.async pipeline of raw f32 A (stride 40 -> conflict-free LDS.64
// fragment loads) + pre-converted bf16 W chunks.  8 warps x (16 rows x 64).
// ---------------------------------------------------------------------------
#define AF_STR 40           // f32 words per row (160B); conflict-free frags
#define AF_SZ  (128 * AF_STR)       // words per stage
#define WS_STR 72
#define WS_SZ  (32 * WS_STR)        // bf16 per stage
#define NCH    16

__global__ __launch_bounds__(256)
void gemm_kernel(const float* __restrict__ A, const float* __restrict__ bias) {
    __shared__ float         Af[4][AF_SZ];   // 81920 B
    __shared__ __nv_bfloat16 Ws[4][WS_SZ];   // 18432 B
    __shared__ float bs[NLAB];

    const int tid = threadIdx.x;
    if (tid < NLAB) bs[tid] = bias[tid];

    const int wm = tid >> 5, lane = tid & 31;
    const int grp = lane >> 2, tig = lane & 3;
    const size_t r0 = (size_t)blockIdx.x * 128;

    const uint32_t af_b = smem_u32(&Af[0][0]);
    const uint32_t ws_b = smem_u32(&Ws[0][0]);
    const char* Abase = (const char*)(A + r0 * DIN);
    const char* Wbase = (const char*)g_Wbf;

    // cp.async mapping: A chunk = 1024 float4 (4/thread); W chunk = 256 float4 (1/thread)
    const int a_row = tid >> 3, a_c4 = tid & 7;          // +32 rows per pass
    const int w_row = tid >> 3, w_c8 = tid & 7;

#define ISSUE(c, st)                                                            \
    do {                                                                        \
        const char* Ag = Abase + (size_t)(c) * 128;                             \
        _Pragma("unroll")                                                       \
        for (int p = 0; p < 4; p++) {                                           \
            int row = a_row + p * 32;                                           \
            cp16(af_b + (uint32_t)((st) * AF_SZ + row * AF_STR + a_c4 * 4) * 4, \
                 Ag + (size_t)row * 2048 + a_c4 * 16);                          \
        }                                                                       \
        cp16(ws_b + (uint32_t)((st) * WS_SZ + w_row * WS_STR + w_c8 * 8) * 2,   \
             Wbase + ((c) * 32 + w_row) * 128 + w_c8 * 16);                     \
        asm volatile("cp.async.commit_group;");                                 \
    } while (0)

    float acc[8][4] = {};

    ISSUE(0, 0);
    ISSUE(1, 1);
    ISSUE(2, 2);

#pragma unroll 1
    for (int c = 0; c < NCH; c++) {
        asm volatile("cp.async.wait_group 2;");
        __syncthreads();
        if (c + 3 < NCH) ISSUE(c + 3, (c + 3) & 3);

        const int st = c & 3;
        const float* af = Af[st];
        const uint32_t wsb = ws_b + (uint32_t)(st * WS_SZ) * 2;

#pragma unroll
        for (int kk = 0; kk < 2; kk++) {
            const int k0 = kk * 16 + tig * 2;
            uint32_t a[4], bbv[4][4];
            {
                float2 p00 = *(const float2*)&af[(wm * 16 + grp)     * AF_STR + k0];
                float2 p10 = *(const float2*)&af[(wm * 16 + grp + 8) * AF_STR + k0];
                float2 p01 = *(const float2*)&af[(wm * 16 + grp)     * AF_STR + k0 + 8];
                float2 p11 = *(const float2*)&af[(wm * 16 + grp + 8) * AF_STR + k0 + 8];
                a[0] = packbf(p00.x, p00.y);
                a[1] = packbf(p10.x, p10.y);
                a[2] = packbf(p01.x, p01.y);
                a[3] = packbf(p11.x, p11.y);
            }
#pragma unroll
            for (int nt = 0; nt < 4; nt++)
                ldsm_x4_t(bbv[nt], wsb + (uint32_t)((kk * 16 + (lane & 15)) * WS_STR
                                                    + nt * 16 + ((lane >> 4) << 3)) * 2);
#pragma unroll
            for (int nt = 0; nt < 4; nt++) {
                mma_bf16(acc[nt * 2],     a, &bbv[nt][0]);
                mma_bf16(acc[nt * 2 + 1], a, &bbv[nt][2]);
            }
        }
    }
#undef ISSUE

    // Epilogue: +bias, row max, exp, bf16 store + g_S
    __syncthreads();   // protect smem reuse
    const int r0l = wm * 16 + grp;
    float v0[16], v1[16];
    float m0 = -1e30f, m1 = -1e30f;
#pragma unroll
    for (int nb = 0; nb < 8; nb++) {
#pragma unroll
        for (int h = 0; h < 2; h++) {
            int cc = nb * 8 + tig * 2 + h;
            float x0 = acc[nb][h]     + bs[cc];
            float x1 = acc[nb][2 + h] + bs[cc];
            v0[nb * 2 + h] = x0; v1[nb * 2 + h] = x1;
            m0 = fmaxf(m0, x0); m1 = fmaxf(m1, x1);
        }
    }
    m0 = fmaxf(m0, __shfl_xor_sync(0xffffffffu, m0, 1));
    m0 = fmaxf(m0, __shfl_xor_sync(0xffffffffu, m0, 2));
    m1 = fmaxf(m1, __shfl_xor_sync(0xffffffffu, m1, 1));
    m1 = fmaxf(m1, __shfl_xor_sync(0xffffffffu, m1, 2));

    __nv_bfloat16* stage = (__nv_bfloat16*)Af;
#pragma unroll
    for (int nb = 0; nb < 8; nb++) {
        *(uint32_t*)&stage[r0l * 72 + nb * 8 + tig * 2] =
            packbf(__expf(v0[nb * 2] - m0), __expf(v0[nb * 2 + 1] - m0));
        *(uint32_t*)&stage[(r0l + 8) * 72 + nb * 8 + tig * 2] =
            packbf(__expf(v1[nb * 2] - m1), __expf(v1[nb * 2 + 1] - m1));
    }
    if (tig == 0) { g_S[r0 + r0l] = m0; g_S[r0 + r0l + 8] = m1; }
    __syncwarp();
#pragma unroll
    for (int p = 0; p < 4; p++) {
        int q = lane + 32 * p;
        int rr = q >> 3, c16 = q & 7;
        uint4 d = *(uint4*)&stage[(wm * 16 + rr) * 72 + c16 * 8];
        *(uint4*)&g_E[(r0 + wm * 16 + rr) * 64 + c16 * 8] = d;
    }
}

// ---------------------------------------------------------------------------
// Subtree kernel: CTA = (batch b, subtree j of 8).  Loads 128 leaves, reduces
// 7 levels (P=64..1) entirely in smem, writes node (7+j) + accumulated shift.
// ---------------------------------------------------------------------------
__global__ __launch_bounds__(256)
void subtree_kernel() {
    __shared__ __nv_bfloat16 Cur[128 * 72];   // children/level values (ldsm layout)
    __shared__ __nv_bfloat16 Tb[64 * 72];     // expTb (ldsm layout)
    __shared__ __nv_bfloat16 Par[64 * 64];    // parent emission rows (linear)
    __shared__ float warpS[8];

    const int tid = threadIdx.x;
    const int wm = tid >> 5, lane = tid & 31;
    const int grp = lane >> 2, tig = lane & 3;
    const int b = blockIdx.x >> 3, j = blockIdx.x & 7;
    const size_t nb_base = (size_t)b * NNODES;

    const uint32_t cur_b = smem_u32(Cur), tb_b = smem_u32(Tb);
    const uint32_t par_b = smem_u32(Par);

    const char* Lg = (const char*)(g_E + (nb_base + 1023 + 128 * j) * 64);
    for (int q = tid; q < 1024; q += 256) {
        int r = q >> 3, c = q & 7;
        cp16(cur_b + (uint32_t)(r * 72 + c * 8) * 2, Lg + q * 16);
    }
    const char* Tg = (const char*)g_expTb;
    for (int q = tid; q < 512; q += 256) {
        int r = q >> 3, c = q & 7;
        cp16(tb_b + (uint32_t)(r * 72 + c * 8) * 2, Tg + q * 16);
    }
    asm volatile("cp.async.commit_group;");
    asm volatile("cp.async.wait_group 0;");
    __syncthreads();

    float lsum = 0.f;

#pragma unroll 1
    for (int P = 64; P >= 1; P >>= 1) {
        const int nbase = 8 * P - 1 + P * j;
        const int active = (wm * 16) < 2 * P;

        {
            const char* Pg = (const char*)(g_E + (nb_base + nbase) * 64);
            for (int q = tid; q < P * 8; q += 256)
                cp16(par_b + (uint32_t)(q * 16), Pg + q * 16);
            asm volatile("cp.async.commit_group;");
        }

        float acc[8][4];
#pragma unroll
        for (int nb = 0; nb < 8; nb++)
#pragma unroll
            for (int i = 0; i < 4; i++) acc[nb][i] = 0.f;

        if (active) {
#pragma unroll
            for (int kk = 0; kk < 4; kk++) {
                uint32_t a[4], bbv[4][4];
                ldsm_x4(a, cur_b + (uint32_t)((wm * 16 + (lane & 15)) * 72
                                              + kk * 16 + ((lane >> 4) << 3)) * 2);
#pragma unroll
                for (int nt = 0; nt < 4; nt++)
                    ldsm_x4_t(bbv[nt], tb_b + (uint32_t)((kk * 16 + (lane & 15)) * 72
                                                         + nt * 16 + ((lane >> 4) << 3)) * 2);
#pragma unroll
                for (int nt = 0; nt < 4; nt++) {
                    mma_bf16(acc[nt * 2],     a, &bbv[nt][0]);
                    mma_bf16(acc[nt * 2 + 1], a, &bbv[nt][2]);
                }
            }
        }
        asm volatile("cp.async.wait_group 0;");
        __syncthreads();

        if (active) {
            const int p0 = wm * 8 + (grp >> 1);
            const int p1 = p0 + 4;
            const bool ok0 = p0 < P, ok1 = p1 < P;

            float q0[16], q1[16];
            float C0 = 0.f, C1 = 0.f;
#pragma unroll
            for (int nb = 0; nb < 8; nb++) {
                float s00 = acc[nb][0], s01 = acc[nb][1];
                float s10 = acc[nb][2], s11 = acc[nb][3];
                float p00 = s00 * __shfl_xor_sync(0xffffffffu, s00, 4);
                float p01 = s01 * __shfl_xor_sync(0xffffffffu, s01, 4);
                float p10 = s10 * __shfl_xor_sync(0xffffffffu, s10, 4);
                float p11 = s11 * __shfl_xor_sync(0xffffffffu, s11, 4);
                uint32_t e0u = ok0 ? *(const uint32_t*)&Par[p0 * 64 + nb * 8 + tig * 2] : 0u;
                uint32_t e1u = ok1 ? *(const uint32_t*)&Par[p1 * 64 + nb * 8 + tig * 2] : 0u;
                __nv_bfloat162 e0b, e1b;
                memcpy(&e0b, &e0u, 4); memcpy(&e1b, &e1u, 4);
                q0[nb * 2]     = __bfloat162float(e0b.x) * p00;
                q0[nb * 2 + 1] = __bfloat162float(e0b.y) * p01;
                q1[nb * 2]     = __bfloat162float(e1b.x) * p10;
                q1[nb * 2 + 1] = __bfloat162float(e1b.y) * p11;
                C0 = fmaxf(C0, fmaxf(q0[nb * 2], q0[nb * 2 + 1]));
                C1 = fmaxf(C1, fmaxf(q1[nb * 2], q1[nb * 2 + 1]));
            }
            C0 = fmaxf(C0, __shfl_xor_sync(0xffffffffu, C0, 1));
            C0 = fmaxf(C0, __shfl_xor_sync(0xffffffffu, C0, 2));
            C1 = fmaxf(C1, __shfl_xor_sync(0xffffffffu, C1, 1));
            C1 = fmaxf(C1, __shfl_xor_sync(0xffffffffu, C1, 2));
            float i0 = __fdividef(1.0f, C0), i1 = __fdividef(1.0f, C1);

            if (!(grp & 1)) {
                if (ok0) {
#pragma unroll
                    for (int nb = 0; nb < 8; nb++)
                        *(uint32_t*)&Cur[p0 * 72 + nb * 8 + tig * 2] =
                            packbf(q0[nb * 2] * i0, q0[nb * 2 + 1] * i0);
                }
                if (ok1) {
#pragma unroll
                    for (int nb = 0; nb < 8; nb++)
                        *(uint32_t*)&Cur[p1 * 72 + nb * 8 + tig * 2] =
                            packbf(q1[nb * 2] * i1, q1[nb * 2 + 1] * i1);
                }
                if (tig == 0) {
                    if (ok0) lsum += __logf(C0);
                    if (ok1) lsum += __logf(C1);
                }
            }
        }
        __syncthreads();
    }

    if (tid < 8)
        *(uint4*)&g_E[(nb_base + 7 + j) * 64 + tid * 8] = *(uint4*)&Cur[tid * 8];

#pragma unroll
    for (int o = 16; o > 0; o >>= 1) lsum += __shfl_xor_sync(0xffffffffu, lsum, o);
    if (lane == 0) warpS[wm] = lsum;
    __syncthreads();
    if (tid == 0) {
        float t = 0.f;
        for (int i = 0; i < 8; i++) t += warpS[i];
        g_S[nb_base + 7 + j] += t;
    }
}

// ---------------------------------------------------------------------------
// Tail: one CTA per batch. g_S sum + levels over nodes 0..14 + root output.
// ---------------------------------------------------------------------------
__global__ __launch_bounds__(256)
void tail_kernel(float* __restrict__ out) {
    __shared__ float  Eb[15 * 64];
    __shared__ float2 Ept[NLAB * 32];
    __shared__ float  warpS[8];
    __shared__ float  sGlob;

    const int tid = threadIdx.x;
    const int wm = tid >> 5, lane = tid & 31;
    const int b = blockIdx.x;

    for (int i = tid; i < NLAB * 32; i += 256) Ept[i] = g_expT[i];
    const uint32_t* src = (const uint32_t*)(g_E + (size_t)b * NNODES * 64);
    for (int i = tid; i < 480; i += 256) {
        uint32_t v = src[i];
        __nv_bfloat162 bb; memcpy(&bb, &v, 4);
        Eb[2 * i]     = __bfloat162float(bb.x);
        Eb[2 * i + 1] = __bfloat162float(bb.y);
    }
    float s = 0.f;
    const float* Sb = g_S + (size_t)b * NNODES;
    for (int i = tid; i < NNODES; i += 256) s += Sb[i];
#pragma unroll
    for (int o = 16; o > 0; o >>= 1) s += __shfl_xor_sync(0xffffffffu, s, o);
    if (lane == 0) warpS[wm] = s;
    __syncthreads();
    if (tid == 0) {
        float t = 0.f;
        for (int i = 0; i < 8; i++) t += warpS[i];
        sGlob = t;
    }
    __syncthreads();

    if (wm == 0) {
        float wlog = 0.f;
        const int nodes[6] = {3, 4, 5, 6, 1, 2};
#pragma unroll 1
        for (int t = 0; t < 6; t++) {
            int p = nodes[t], cL = 2 * p + 1, cR = 2 * p + 2;
            float aL0 = 0.f, aL1 = 0.f, aR0 = 0.f, aR1 = 0.f;
#pragma unroll
            for (int k = 0; k < NLAB; k++) {
                float2 tt = Ept[k * 32 + lane];
                float uL = Eb[cL * 64 + k], uR = Eb[cR * 64 + k];
                aL0 = fmaf(tt.x, uL, aL0); aL1 = fmaf(tt.y, uL, aL1);
                aR0 = fmaf(tt.x, uR, aR0); aR1 = fmaf(tt.y, uR, aR1);
            }
            float q0 = Eb[p * 64 + lane]      * aL0 * aR0;
            float q1 = Eb[p * 64 + lane + 32] * aL1 * aR1;
            float C = fmaxf(q0, q1);
#pragma unroll
            for (int o = 16; o > 0; o >>= 1) C = fmaxf(C, __shfl_xor_sync(0xffffffffu, C, o));
            float inv = __fdividef(1.0f, C);
            Eb[p * 64 + lane]      = q0 * inv;
            Eb[p * 64 + lane + 32] = q1 * inv;
            wlog += __logf(C);
            __syncwarp();
        }
        float aL0 = 0.f, aL1 = 0.f, aR0 = 0.f, aR1 = 0.f;
#pragma unroll
        for (int k = 0; k < NLAB; k++) {
            float2 tt = Ept[k * 32 + lane];
            float uL = Eb[64 + k], uR = Eb[128 + k];
            aL0 = fmaf(tt.x, uL, aL0); aL1 = fmaf(tt.y, uL, aL1);
            aR0 = fmaf(tt.x, uR, aR0); aR1 = fmaf(tt.y, uR, aR1);
        }
        float q0 = Eb[lane]      * aL0 * aR0;
        float q1 = Eb[lane + 32] * aL1 * aR1;
        float S = sGlob + wlog;
        out[b * NLAB + lane]      = S + __logf(q0);
        out[b * NLAB + lane + 32] = S + __logf(q1);
    }
}

// ---------------------------------------------------------------------------
// Launcher
// ---------------------------------------------------------------------------
extern "C" void kernel_launch(void* const* d_in, const int* in_sizes, int n_in,
                              void* d_out, int out_size) {
    const float* hidden = (const float*)d_in[0];
    const float* W      = (const float*)d_in[1];
    const float* bias   = (const float*)d_in[2];
    const float* trans  = (const float*)d_in[3];
    float* out = (float*)d_out;

    init_all<<<128, 256>>>(trans, W);
    gemm_kernel<<<NNODES, 256>>>(hidden, bias);
    subtree_kernel<<<BATCH * 8, 256>>>();
    tail_kernel<<<BATCH, 256>>>(out);
}